// round 1
// baseline (speedup 1.0000x reference)
#include <cuda_runtime.h>
#include <math.h>

#define Bsz 256
#define Tsz 128
#define EMB 256
#define HID 512
#define VOC 1004
#define FCI 2048
#define BT  (Bsz*Tsz)
#define G4  (4*HID)

// ------------------------- device scratch -------------------------
__device__ __align__(16) float g_feats   [Bsz*EMB];
__device__ __align__(16) float g_ctx_base[Bsz*EMB];
__device__ __align__(16) float g_gate_base[Bsz*G4];
__device__ __align__(16) float g_ctx     [(size_t)BT*EMB];      // 33.5 MB
__device__ __align__(16) float g_gatesX  [(size_t)BT*G4];       // 268 MB
__device__ __align__(16) float g_hseq    [(size_t)BT*HID];      // 67 MB
__device__ __align__(16) float g_h[2][Bsz*HID];
__device__ __align__(16) float g_c[Bsz*HID];

// ------------------------- init -------------------------
__global__ void init_state_kernel() {
    int i = blockIdx.x*blockDim.x + threadIdx.x;
    if (i < Bsz*HID) { g_h[0][i] = 0.f; g_c[i] = 0.f; }
}

// ------------------------- generic NT SGEMM -------------------------
// C[m,n] = sum_k A[m,k]*W[n,k] + bias[n] + rowAdd[m/rowDiv, n]
// BM=BN=64, BK=16, 256 threads, 4x4 per thread, double-buffered regs.
__global__ __launch_bounds__(256)
void gemm64(const float* __restrict__ A, int lda,
            const float* __restrict__ W, int ldw,
            float* __restrict__ C, int ldc,
            int M, int N, int K,
            const float* __restrict__ bias,
            const float* __restrict__ rowAdd, int rowDiv, int rowLd)
{
    __shared__ float As[16][68];
    __shared__ float Ws[16][68];

    const int n0 = blockIdx.x*64, m0 = blockIdx.y*64;
    const int t  = threadIdx.x;
    const int lr = t>>2, lc = (t&3)*4;          // loader: row, col(float4)
    const int tx = t&15, ty = t>>4;
    const int cm = ty*4, cn = tx*4;

    float acc[4][4] = {};

    const float* Ap = A + (size_t)(m0+lr)*lda + lc;
    const bool   wok = (n0+lr) < N;
    const float* Wp = W + (size_t)(wok ? (n0+lr) : 0)*ldw + lc;

    float4 av = *(const float4*)Ap;
    float4 wv = wok ? *(const float4*)Wp : make_float4(0,0,0,0);

    for (int k0 = 0; k0 < K; k0 += 16) {
        As[lc+0][lr]=av.x; As[lc+1][lr]=av.y; As[lc+2][lr]=av.z; As[lc+3][lr]=av.w;
        Ws[lc+0][lr]=wv.x; Ws[lc+1][lr]=wv.y; Ws[lc+2][lr]=wv.z; Ws[lc+3][lr]=wv.w;
        __syncthreads();

        if (k0 + 16 < K) {
            av = *(const float4*)(Ap + k0 + 16);
            wv = wok ? *(const float4*)(Wp + k0 + 16) : make_float4(0,0,0,0);
        }

        #pragma unroll
        for (int kk = 0; kk < 16; kk++) {
            float4 a = *(const float4*)&As[kk][cm];
            float4 w = *(const float4*)&Ws[kk][cn];
            acc[0][0]+=a.x*w.x; acc[0][1]+=a.x*w.y; acc[0][2]+=a.x*w.z; acc[0][3]+=a.x*w.w;
            acc[1][0]+=a.y*w.x; acc[1][1]+=a.y*w.y; acc[1][2]+=a.y*w.z; acc[1][3]+=a.y*w.w;
            acc[2][0]+=a.z*w.x; acc[2][1]+=a.z*w.y; acc[2][2]+=a.z*w.z; acc[2][3]+=a.z*w.w;
            acc[3][0]+=a.w*w.x; acc[3][1]+=a.w*w.y; acc[3][2]+=a.w*w.z; acc[3][3]+=a.w*w.w;
        }
        __syncthreads();
    }

    // epilogue
    #pragma unroll
    for (int i = 0; i < 4; i++) {
        const int gm = m0 + cm + i;
        float v[4];
        #pragma unroll
        for (int j = 0; j < 4; j++) {
            const int gn = n0 + cn + j;
            float x = acc[i][j];
            if (gn < N) {
                if (bias)   x += bias[gn];
                if (rowAdd) x += rowAdd[(size_t)(gm / rowDiv) * rowLd + gn];
            }
            v[j] = x;
        }
        if (n0 + cn + 3 < N) {
            float4 o; o.x=v[0]; o.y=v[1]; o.z=v[2]; o.w=v[3];
            *(float4*)(C + (size_t)gm*ldc + n0 + cn) = o;
        } else {
            #pragma unroll
            for (int j = 0; j < 4; j++) {
                const int gn = n0 + cn + j;
                if (gn < N) C[(size_t)gm*ldc + gn] = v[j];
            }
        }
    }
}

// ------------------------- fused LSTM step -------------------------
// gates(b,h,4) = gatesX[b,t,:] + h_in @ W_hh^T + b_hh ; then cell update.
// Tile: 32 batch x 32 hidden, all 4 gates per CTA (128 W rows). 256 threads.
// grid = (B/32, HID/32) = (8,16) = 128 CTAs.
__global__ __launch_bounds__(256)
void lstm_step(const float* __restrict__ W_hh,
               const float* __restrict__ b_hh,
               int tstep)
{
    __shared__ float As[16][36];
    __shared__ float Ws[16][132];

    const float* __restrict__ h_in  = g_h[tstep & 1];
    float*       __restrict__ h_out = g_h[(tstep+1) & 1];

    const int b0 = blockIdx.x*32, h0 = blockIdx.y*32;
    const int t  = threadIdx.x;
    const int lr = t>>2, lc = (t&3)*4;     // A loader (first 128 threads)
    const int th = t & 31;                 // hidden within tile
    const int tmb = (t>>5)*4;              // batch group (4 rows)

    float acc[4][4] = {};                  // [gate][m]

    // B loader: 128 rows (4 gates x 32 h), 16 k-floats each = 512 float4
    const int i0 = t,      br0 = i0>>2, bc0 = (i0&3)*4, ga0 = br0>>5, j0 = br0&31;
    const int i1 = t+256,  br1 = i1>>2, bc1 = (i1&3)*4, ga1 = br1>>5, j1 = br1&31;
    const float* Wp0 = W_hh + (size_t)(ga0*HID + h0 + j0)*HID + bc0;
    const float* Wp1 = W_hh + (size_t)(ga1*HID + h0 + j1)*HID + bc1;
    const float* Ap  = h_in + (size_t)(b0 + lr)*HID + lc;

    float4 av = (t < 128) ? *(const float4*)Ap : make_float4(0,0,0,0);
    float4 wv0 = *(const float4*)Wp0;
    float4 wv1 = *(const float4*)Wp1;

    for (int k0 = 0; k0 < HID; k0 += 16) {
        if (t < 128) {
            As[lc+0][lr]=av.x; As[lc+1][lr]=av.y; As[lc+2][lr]=av.z; As[lc+3][lr]=av.w;
        }
        Ws[bc0+0][br0]=wv0.x; Ws[bc0+1][br0]=wv0.y; Ws[bc0+2][br0]=wv0.z; Ws[bc0+3][br0]=wv0.w;
        Ws[bc1+0][br1]=wv1.x; Ws[bc1+1][br1]=wv1.y; Ws[bc1+2][br1]=wv1.z; Ws[bc1+3][br1]=wv1.w;
        __syncthreads();

        if (k0 + 16 < HID) {
            if (t < 128) av = *(const float4*)(Ap + k0 + 16);
            wv0 = *(const float4*)(Wp0 + k0 + 16);
            wv1 = *(const float4*)(Wp1 + k0 + 16);
        }

        #pragma unroll
        for (int kk = 0; kk < 16; kk++) {
            float4 a = *(const float4*)&As[kk][tmb];
            float wi = Ws[kk][      th];
            float wf = Ws[kk][ 32 + th];
            float wg = Ws[kk][ 64 + th];
            float wo = Ws[kk][ 96 + th];
            acc[0][0]+=a.x*wi; acc[0][1]+=a.y*wi; acc[0][2]+=a.z*wi; acc[0][3]+=a.w*wi;
            acc[1][0]+=a.x*wf; acc[1][1]+=a.y*wf; acc[1][2]+=a.z*wf; acc[1][3]+=a.w*wf;
            acc[2][0]+=a.x*wg; acc[2][1]+=a.y*wg; acc[2][2]+=a.z*wg; acc[2][3]+=a.w*wg;
            acc[3][0]+=a.x*wo; acc[3][1]+=a.y*wo; acc[3][2]+=a.z*wo; acc[3][3]+=a.w*wo;
        }
        __syncthreads();
    }

    // ---- fused LSTM cell epilogue ----
    const int h = h0 + th;
    const float bi = b_hh[h];
    const float bf = b_hh[HID   + h];
    const float bg = b_hh[2*HID + h];
    const float bo = b_hh[3*HID + h];

    #pragma unroll
    for (int i = 0; i < 4; i++) {
        const int b = b0 + tmb + i;
        const size_t base = ((size_t)b*Tsz + tstep)*G4;
        float gi = acc[0][i] + g_gatesX[base +           h] + bi;
        float gf = acc[1][i] + g_gatesX[base + HID   +   h] + bf;
        float gg = acc[2][i] + g_gatesX[base + 2*HID +   h] + bg;
        float go = acc[3][i] + g_gatesX[base + 3*HID +   h] + bo;

        float si = 1.f/(1.f + expf(-gi));
        float sf = 1.f/(1.f + expf(-gf));
        float so = 1.f/(1.f + expf(-go));

        const int ch = b*HID + h;
        float cnew = sf*g_c[ch] + si*tanhf(gg);
        float hnew = so*tanhf(cnew);
        g_c[ch]   = cnew;
        h_out[ch] = hnew;
        g_hseq[((size_t)b*Tsz + tstep)*HID + h] = hnew;
    }
}

// ------------------------- launch -------------------------
extern "C" void kernel_launch(void* const* d_in, const int* in_sizes, int n_in,
                              void* d_out, int out_size)
{
    const float* images   = (const float*)d_in[0];
    const float* captions = (const float*)d_in[1];
    const float* W_fc  = (const float*)d_in[2];
    const float* b_fc  = (const float*)d_in[3];
    const float* W_att = (const float*)d_in[4];
    const float* b_att = (const float*)d_in[5];
    const float* W_ih  = (const float*)d_in[6];
    const float* b_ih  = (const float*)d_in[7];
    const float* W_hh  = (const float*)d_in[8];
    const float* b_hh  = (const float*)d_in[9];
    const float* W_out = (const float*)d_in[10];
    const float* b_out = (const float*)d_in[11];
    float* out = (float*)d_out;

    float *p_feats, *p_ctxb, *p_gateb, *p_ctx, *p_gatesX, *p_hseq;
    cudaGetSymbolAddress((void**)&p_feats,  g_feats);
    cudaGetSymbolAddress((void**)&p_ctxb,   g_ctx_base);
    cudaGetSymbolAddress((void**)&p_gateb,  g_gate_base);
    cudaGetSymbolAddress((void**)&p_ctx,    g_ctx);
    cudaGetSymbolAddress((void**)&p_gatesX, g_gatesX);
    cudaGetSymbolAddress((void**)&p_hseq,   g_hseq);

    // zero h0, c0
    init_state_kernel<<<(Bsz*HID + 255)/256, 256>>>();

    // feats = images @ W_fc^T + b_fc            [256,256] K=2048
    gemm64<<<dim3(EMB/64, Bsz/64), 256>>>(images, FCI, W_fc, FCI, p_feats, EMB,
                                          Bsz, EMB, FCI, b_fc, nullptr, 1, 0);

    // ctx_base = feats @ W_att[:, :256]^T + b_att
    gemm64<<<dim3(EMB/64, Bsz/64), 256>>>(p_feats, EMB, W_att, EMB+HID, p_ctxb, EMB,
                                          Bsz, EMB, EMB, b_att, nullptr, 1, 0);

    // gate_base = feats @ W_ih[:, :256]^T + b_ih
    gemm64<<<dim3(G4/64, Bsz/64), 256>>>(p_feats, EMB, W_ih, 2*EMB, p_gateb, G4,
                                         Bsz, G4, EMB, b_ih, nullptr, 1, 0);

    // ctx[b,t] = captions @ W_att[:, 256:]^T + ctx_base[b]   M=32768,N=256,K=512
    gemm64<<<dim3(EMB/64, BT/64), 256>>>(captions, HID, W_att + EMB, EMB+HID, p_ctx, EMB,
                                         BT, EMB, HID, nullptr, p_ctxb, Tsz, EMB);

    // gatesX[b,t] = ctx @ W_ih[:, 256:]^T + gate_base[b]     M=32768,N=2048,K=256
    gemm64<<<dim3(G4/64, BT/64), 256>>>(p_ctx, EMB, W_ih + EMB, 2*EMB, p_gatesX, G4,
                                        BT, G4, EMB, nullptr, p_gateb, Tsz, G4);

    // sequential recurrence, fused GEMM + cell
    for (int t = 0; t < Tsz; t++)
        lstm_step<<<dim3(Bsz/32, HID/32), 256>>>(W_hh, b_hh, t);

    // out = hseq @ W_out^T + b_out              M=32768,N=1004,K=512
    gemm64<<<dim3((VOC+63)/64, BT/64), 256>>>(p_hseq, HID, W_out, HID, out, VOC,
                                              BT, VOC, HID, b_out, nullptr, 1, 0);
}